// round 10
// baseline (speedup 1.0000x reference)
#include <cuda_runtime.h>
#include <cstdint>

#define NN 12288
#define DD 128
#define JSPLIT 3
#define JLEN (NN / JSPLIT)      // 4096
#define KC 32
#define NC (JLEN / KC)          // 128 chunks
#define MB 128
#define MBLK (NN / MB)          // 96

// dynamic smem layout (floats)
#define SP_OFF   0                          // sP[2][128][36]
#define SVP_OFF  (2 * 128 * 36)             // sVp[2][4][128][8]
#define DEN_OFF  (SVP_OFF + 2 * 4 * 128 * 8)
#define SMEM_FLOATS (DEN_OFF + 128)
#define SMEM_BYTES  (SMEM_FLOATS * 4)       // 70144 B

// ---------------- static scratch ----------------
__device__ float g_WT[DD * DD];
__device__ float g_V [(size_t)NN * DD];
__device__ float g_Vr[(size_t)NN * DD];            // tf32-pre-rounded V
__device__ float g_Vp[(size_t)NN * DD];            // pair-permuted Vr: [jg][d][t4]{k,k+4}
__device__ float g_s[NN], g_t[NN];
__device__ float g_Es[NN], g_Et[NN], g_Fs[NN], g_Ft[NN];
__device__ float g_parts[JSPLIT][(size_t)NN * DD];
__device__ float g_dparts[JSPLIT][NN];

__device__ __forceinline__ float totf32(float x) {
    float r; asm("cvt.rna.tf32.f32 %0, %1;" : "=f"(r) : "f"(x)); return r;
}
__device__ __forceinline__ void mma_tf32_16x8x8(float* c, const float* a, const float* b) {
    asm volatile(
        "mma.sync.aligned.m16n8k8.row.col.f32.tf32.tf32.f32 "
        "{%0,%1,%2,%3}, {%4,%5,%6,%7}, {%8,%9}, {%0,%1,%2,%3};"
        : "+f"(c[0]), "+f"(c[1]), "+f"(c[2]), "+f"(c[3])
        : "f"(a[0]), "f"(a[1]), "f"(a[2]), "f"(a[3]), "f"(b[0]), "f"(b[1]));
}
__device__ __forceinline__ void cp_async16(uint32_t dst, const void* src) {
    asm volatile("cp.async.ca.shared.global [%0], [%1], 16;"
                 :: "r"(dst), "l"(src) : "memory");
}
__device__ __forceinline__ void cp_commit() {
    asm volatile("cp.async.commit_group;" ::: "memory");
}
__device__ __forceinline__ void cp_wait0() {
    asm volatile("cp.async.wait_group 0;" ::: "memory");
}
__device__ __forceinline__ void pf_l1(const void* p) {
    asm volatile("prefetch.global.L1 [%0];" :: "l"(p));
}

// ---------------- Kernel A0: transpose W ----------------
__global__ void k_transW(const float* __restrict__ W) {
    int i = blockIdx.x * 256 + threadIdx.x;
    if (i < DD * DD) {
        int d = i >> 7, k = i & 127;
        g_WT[k * DD + d] = W[i];
    }
}

// ---------------- Kernel A: e_new = emb @ W^T (+ tf32-rounded copy) ----------------
__global__ __launch_bounds__(256) void k_enew(const float* __restrict__ emb) {
    const int rb = blockIdx.x * 16;
    const int tid = threadIdx.x;
    __shared__ float es[16][128];
    for (int i = tid; i < 16 * 128; i += 256) {
        int r = i >> 7, k = i & 127;
        es[r][k] = emb[(size_t)(rb + r) * DD + k];
    }
    __syncthreads();
    const int rg = tid >> 5;
    const int dq = tid & 31;
    float acc[2][4];
    #pragma unroll
    for (int i = 0; i < 2; i++)
        #pragma unroll
        for (int j = 0; j < 4; j++) acc[i][j] = 0.f;
    #pragma unroll 4
    for (int k = 0; k < 128; ++k) {
        float4 wv = *(const float4*)&g_WT[k * DD + 4 * dq];
        float e0 = es[rg * 2 + 0][k];
        float e1 = es[rg * 2 + 1][k];
        acc[0][0] += e0 * wv.x; acc[0][1] += e0 * wv.y; acc[0][2] += e0 * wv.z; acc[0][3] += e0 * wv.w;
        acc[1][0] += e1 * wv.x; acc[1][1] += e1 * wv.y; acc[1][2] += e1 * wv.z; acc[1][3] += e1 * wv.w;
    }
    #pragma unroll
    for (int rr = 0; rr < 2; ++rr) {
        size_t row = (size_t)(rb + rg * 2 + rr) * DD;
        *(float4*)&g_V[row + 4 * dq] = make_float4(acc[rr][0], acc[rr][1], acc[rr][2], acc[rr][3]);
        *(float4*)&g_Vr[row + 4 * dq] = make_float4(totf32(acc[rr][0]), totf32(acc[rr][1]),
                                                    totf32(acc[rr][2]), totf32(acc[rr][3]));
    }
}

// ---------------- Kernel A2: pair-permute Vr -> Vp ----------------
// g_Vp[((jg*128 + d)*4 + t4)*2 + {0,1}] = Vr[8*jg + t4][d], Vr[8*jg + t4 + 4][d]
// One block per jg (512 threads): tid -> t4 = tid>>7, d = tid&127 (coalesced reads).
__global__ __launch_bounds__(512) void k_vperm() {
    const int jg = blockIdx.x;
    const int t4 = threadIdx.x >> 7;
    const int d  = threadIdx.x & 127;
    float lo = g_Vr[(size_t)(8 * jg + t4    ) * DD + d];
    float hi = g_Vr[(size_t)(8 * jg + t4 + 4) * DD + d];
    *(float2*)&g_Vp[(size_t)((jg * 128 + d) * 4 + t4) * 2] = make_float2(lo, hi);
}

// ---------------- Kernel B: per-row scalars ----------------
__global__ void k_scal(const float* __restrict__ a) {
    const int i = blockIdx.x;
    const int tid = threadIdx.x;  // 128
    float v = g_V[(size_t)i * DD + tid];
    float sp = v * a[tid];
    float tp = v * a[DD + tid];
    #pragma unroll
    for (int off = 16; off; off >>= 1) {
        sp += __shfl_down_sync(0xffffffffu, sp, off);
        tp += __shfl_down_sync(0xffffffffu, tp, off);
    }
    __shared__ float rs[4], rt[4];
    int w = tid >> 5;
    if ((tid & 31) == 0) { rs[w] = sp; rt[w] = tp; }
    __syncthreads();
    if (tid == 0) {
        float s = rs[0] + rs[1] + rs[2] + rs[3];
        float t = rt[0] + rt[1] + rt[2] + rt[3];
        g_s[i] = s; g_Es[i] = expf(s); g_Fs[i] = expf(0.01f * s);
        g_t[i] = t; g_Et[i] = expf(t); g_Ft[i] = expf(0.01f * t);
    }
}

// ---------------- Kernel C: pipelined mma.sync tf32  P @ V ----------------
// R7 structure; B tile staged from pair-permuted g_Vp (linear 16KB copy),
// B fragments load as one LDS.64 each.
__global__ __launch_bounds__(256, 2) void k_mma(const int* __restrict__ adj) {
    extern __shared__ float smemf[];
    float (*sPb)[128][36]     = (float (*)[128][36])(smemf + SP_OFF);
    float (*sVp)[4][128][8]   = (float (*)[4][128][8])(smemf + SVP_OFF);
    float* sDen               = smemf + DEN_OFF;
    const uint32_t svp_base = (uint32_t)__cvta_generic_to_shared(smemf + SVP_OFF);

    const int tid = threadIdx.x;
    const int w   = tid >> 5;
    const int l   = tid & 31;
    const int g   = l >> 2;
    const int t4  = l & 3;
    const int rb  = blockIdx.x * MB;
    const int jsp = blockIdx.y;

    const int mrow = (w & 3) * 32;
    const int ncol = (w >> 2) * 64;

    const int r = tid >> 1;
    const int h = tid & 1;
    const float rowS  = g_s [rb + r];
    const float rowEs = g_Es[rb + r];
    const float rowFs = g_Fs[rb + r];
    const size_t adjrow = (size_t)(rb + r) * NN;

    float denreg = 0.f;

    float acc[2][8][4];
    #pragma unroll
    for (int m = 0; m < 2; m++)
        #pragma unroll
        for (int n = 0; n < 8; n++)
            #pragma unroll
            for (int i = 0; i < 4; i++) acc[m][n][i] = 0.f;

    const int jbase = jsp * JLEN;

    // linear 16KB copy of 4 consecutive jg blocks (4096 floats)
    #define STAGE_V(jb_, buf_)                                                    \
        {                                                                         \
            const float* src_ = g_Vp + (size_t)((jb_) >> 3) * 1024;               \
            _Pragma("unroll")                                                     \
            for (int it = 0; it < 4; ++it) {                                      \
                int f_ = tid + it * 256;                                          \
                cp_async16(svp_base + (uint32_t)((buf_) * 4096 + f_ * 4) * 4u,    \
                           src_ + f_ * 4);                                        \
            }                                                                     \
            cp_commit();                                                          \
        }

    #define BUILD_P(jb_, A4_, pb_)                                                \
        {                                                                         \
            float psum_ = 0.f;                                                    \
            _Pragma("unroll")                                                     \
            for (int q_ = 0; q_ < 4; ++q_) {                                      \
                const int col_ = 16 * h + 4 * q_;                                 \
                const int j_   = (jb_) + col_;                                    \
                int4   av  = A4_[q_];                                             \
                float4 tv  = *(const float4*)(g_t  + j_);                         \
                float4 etv = *(const float4*)(g_Et + j_);                         \
                float4 ftv = *(const float4*)(g_Ft + j_);                         \
                float p0 = (av.x > 0) ? ((rowS + tv.x >= 0.f) ? rowEs * etv.x : rowFs * ftv.x) : 0.f; \
                float p1 = (av.y > 0) ? ((rowS + tv.y >= 0.f) ? rowEs * etv.y : rowFs * ftv.y) : 0.f; \
                float p2 = (av.z > 0) ? ((rowS + tv.z >= 0.f) ? rowEs * etv.z : rowFs * ftv.z) : 0.f; \
                float p3 = (av.w > 0) ? ((rowS + tv.w >= 0.f) ? rowEs * etv.w : rowFs * ftv.w) : 0.f; \
                p0 = totf32(p0); p1 = totf32(p1); p2 = totf32(p2); p3 = totf32(p3); \
                psum_ += (p0 + p1) + (p2 + p3);                                   \
                *(float4*)&sPb[pb_][r][col_] = make_float4(p0, p1, p2, p3);       \
            }                                                                     \
            psum_ += __shfl_down_sync(0xffffffffu, psum_, 1);                     \
            if (h == 0) denreg += psum_;                                          \
        }

    // ---- prologue: chunks 0 and 1 ----
    int4 a4[4];
    {
        STAGE_V(jbase, 0);
        #pragma unroll
        for (int q = 0; q < 4; ++q)
            a4[q] = *(const int4*)(adj + adjrow + jbase + 16 * h + 4 * q);
        BUILD_P(jbase, a4, 0);
        STAGE_V(jbase + KC, 1);
        #pragma unroll
        for (int q = 0; q < 4; ++q)
            a4[q] = *(const int4*)(adj + adjrow + jbase + KC + 16 * h + 4 * q);
        cp_wait0();
        __syncthreads();
    }

    for (int c = 0; c < NC; ++c) {
        const int buf = c & 1;

        // ---- overlapped build of P(c+1) ----
        if (c + 1 < NC) {
            BUILD_P(jbase + (c + 1) * KC, a4, buf ^ 1);
            if (c + 2 < NC) {
                if (w == 0) {
                    const int jn = jbase + (c + 2) * KC + 16 * h;
                    pf_l1(g_t + jn); pf_l1(g_Et + jn); pf_l1(g_Ft + jn);
                }
                #pragma unroll
                for (int q = 0; q < 4; ++q)
                    a4[q] = *(const int4*)(adj + adjrow + jbase + (c + 2) * KC + 16 * h + 4 * q);
            }
        }

        // ---- MMA phase on chunk c ----
        #pragma unroll
        for (int ks = 0; ks < 4; ++ks) {
            const int k0 = 8 * ks;
            float afrag[2][4];
            #pragma unroll
            for (int m = 0; m < 2; ++m) {
                const int r0 = mrow + 16 * m;
                afrag[m][0] = sPb[buf][r0 + g    ][k0 + t4    ];
                afrag[m][1] = sPb[buf][r0 + g + 8][k0 + t4    ];
                afrag[m][2] = sPb[buf][r0 + g    ][k0 + t4 + 4];
                afrag[m][3] = sPb[buf][r0 + g + 8][k0 + t4 + 4];
            }
            #pragma unroll
            for (int n = 0; n < 8; ++n) {
                const int n0 = ncol + 8 * n;
                float2 bv = *(const float2*)&sVp[buf][ks][n0 + g][2 * t4];
                float bfrag[2] = { bv.x, bv.y };
                mma_tf32_16x8x8(acc[0][n], afrag[0], bfrag);
                mma_tf32_16x8x8(acc[1][n], afrag[1], bfrag);
            }
        }

        if (c + 1 < NC) {
            cp_wait0();
            __syncthreads();
            if (c + 2 < NC)
                STAGE_V(jbase + (c + 2) * KC, buf);
        }
    }

    // ---- epilogue ----
    float* outp = g_parts[jsp];
    #pragma unroll
    for (int m = 0; m < 2; ++m) {
        #pragma unroll
        for (int n = 0; n < 8; ++n) {
            const int row0 = rb + mrow + 16 * m + g;
            const int col  = ncol + 8 * n + 2 * t4;
            *(float2*)(outp + (size_t)row0 * DD + col) =
                make_float2(acc[m][n][0], acc[m][n][1]);
            *(float2*)(outp + (size_t)(row0 + 8) * DD + col) =
                make_float2(acc[m][n][2], acc[m][n][3]);
        }
    }
    __syncthreads();
    if (h == 0) sDen[r] = denreg;
    __syncthreads();
    if (tid < 128) g_dparts[jsp][rb + tid] = sDen[tid];
}

// ---------------- Kernel D: combine partials, normalize, relu ----------------
__global__ void k_final(float* __restrict__ out) {
    int idx = blockIdx.x * 256 + threadIdx.x;
    int r = idx >> 7;
    float dsum = g_dparts[0][r] + g_dparts[1][r] + g_dparts[2][r];
    float v = g_parts[0][idx] + g_parts[1][idx] + g_parts[2][idx];
    out[idx] = fmaxf(v / dsum, 0.f);
}

// ---------------- launch ----------------
extern "C" void kernel_launch(void* const* d_in, const int* in_sizes, int n_in,
                              void* d_out, int out_size) {
    const float* emb = (const float*)d_in[0];
    const int*   adj = (const int*)d_in[1];
    const float* W   = (const float*)d_in[2];
    const float* a   = (const float*)d_in[3];
    float* out = (float*)d_out;

    cudaFuncSetAttribute(k_mma, cudaFuncAttributeMaxDynamicSharedMemorySize, SMEM_BYTES);

    k_transW<<<(DD * DD + 255) / 256, 256>>>(W);
    k_enew<<<NN / 16, 256>>>(emb);
    k_vperm<<<NN / 8, 512>>>();
    k_scal<<<NN, 128>>>(a);
    k_mma<<<dim3(MBLK, JSPLIT), 256, SMEM_BYTES>>>(adj);
    k_final<<<(NN * DD) / 256, 256>>>(out);
}

// round 13
// speedup vs baseline: 1.9987x; 1.9987x over previous
#include <cuda_runtime.h>
#include <cuda_fp16.h>
#include <cstdint>

#define NN 12288
#define DD 128
#define JSPLIT 3
#define JLEN (NN / JSPLIT)      // 4096
#define KC 32
#define NC (JLEN / KC)          // 128 chunks
#define MB 128
#define MBLK (NN / MB)          // 96

// dynamic smem layout (halves for tiles, floats for den)
#define SPH_BYTES  (2 * 128 * 40 * 2)     // 20480
#define SVH_BYTES  (2 * 128 * 40 * 2)     // 20480
#define SPH_OFF    0
#define SVH_OFF    SPH_BYTES
#define DEN_OFF    (SPH_BYTES + SVH_BYTES)
#define SMEM_BYTES (DEN_OFF + 128 * 4)    // 41472

// ---------------- static scratch ----------------
__device__ float  g_WT[DD * DD];
__device__ float  g_V [(size_t)NN * DD];
__device__ __half g_VhT[(size_t)DD * NN];          // fp16 V transposed: [dim][node]
__device__ float  g_s[NN], g_t[NN];
__device__ float  g_Es[NN], g_Et[NN], g_Fs[NN], g_Ft[NN];
__device__ float  g_parts[JSPLIT][(size_t)NN * DD];
__device__ float  g_dparts[JSPLIT][NN];

__device__ __forceinline__ void mma_f16_16x8x16(float* c, const uint32_t* a,
                                                uint32_t b0, uint32_t b1) {
    asm volatile(
        "mma.sync.aligned.m16n8k16.row.col.f32.f16.f16.f32 "
        "{%0,%1,%2,%3}, {%4,%5,%6,%7}, {%8,%9}, {%0,%1,%2,%3};"
        : "+f"(c[0]), "+f"(c[1]), "+f"(c[2]), "+f"(c[3])
        : "r"(a[0]), "r"(a[1]), "r"(a[2]), "r"(a[3]), "r"(b0), "r"(b1));
}
__device__ __forceinline__ void cp_async16(uint32_t dst, const void* src) {
    asm volatile("cp.async.ca.shared.global [%0], [%1], 16;"
                 :: "r"(dst), "l"(src) : "memory");
}
__device__ __forceinline__ void cp_commit() {
    asm volatile("cp.async.commit_group;" ::: "memory");
}
__device__ __forceinline__ void cp_wait0() {
    asm volatile("cp.async.wait_group 0;" ::: "memory");
}
__device__ __forceinline__ void pf_l1(const void* p) {
    asm volatile("prefetch.global.L1 [%0];" :: "l"(p));
}
__device__ __forceinline__ uint32_t h2u(float lo, float hi) {
    __half2 h = __float22half2_rn(make_float2(lo, hi));
    return *(uint32_t*)&h;
}

// ---------------- Kernel A0: transpose W ----------------
__global__ void k_transW(const float* __restrict__ W) {
    int i = blockIdx.x * 256 + threadIdx.x;
    if (i < DD * DD) {
        int d = i >> 7, k = i & 127;
        g_WT[k * DD + d] = W[i];
    }
}

// ---------------- Kernel A: e_new = emb @ W^T ----------------
__global__ __launch_bounds__(256) void k_enew(const float* __restrict__ emb) {
    const int rb = blockIdx.x * 16;
    const int tid = threadIdx.x;
    __shared__ float es[16][128];
    for (int i = tid; i < 16 * 128; i += 256) {
        int r = i >> 7, k = i & 127;
        es[r][k] = emb[(size_t)(rb + r) * DD + k];
    }
    __syncthreads();
    const int rg = tid >> 5;
    const int dq = tid & 31;
    float acc[2][4];
    #pragma unroll
    for (int i = 0; i < 2; i++)
        #pragma unroll
        for (int j = 0; j < 4; j++) acc[i][j] = 0.f;
    #pragma unroll 4
    for (int k = 0; k < 128; ++k) {
        float4 wv = *(const float4*)&g_WT[k * DD + 4 * dq];
        float e0 = es[rg * 2 + 0][k];
        float e1 = es[rg * 2 + 1][k];
        acc[0][0] += e0 * wv.x; acc[0][1] += e0 * wv.y; acc[0][2] += e0 * wv.z; acc[0][3] += e0 * wv.w;
        acc[1][0] += e1 * wv.x; acc[1][1] += e1 * wv.y; acc[1][2] += e1 * wv.z; acc[1][3] += e1 * wv.w;
    }
    #pragma unroll
    for (int rr = 0; rr < 2; ++rr) {
        size_t row = (size_t)(rb + rg * 2 + rr) * DD;
        *(float4*)&g_V[row + 4 * dq] = make_float4(acc[rr][0], acc[rr][1], acc[rr][2], acc[rr][3]);
    }
}

// ---------------- Kernel A2: transpose V -> fp16 [dim][node] ----------------
__global__ void k_vhT() {
    __shared__ float tile[32][33];
    int nb = blockIdx.x * 32, db = blockIdx.y * 32;
    int tx = threadIdx.x, ty = threadIdx.y;   // 32x8
    #pragma unroll
    for (int i = 0; i < 32; i += 8)
        tile[ty + i][tx] = g_V[(size_t)(nb + ty + i) * DD + db + tx];
    __syncthreads();
    #pragma unroll
    for (int i = 0; i < 32; i += 8)
        g_VhT[(size_t)(db + ty + i) * NN + nb + tx] = __float2half(tile[tx][ty + i]);
}

// ---------------- Kernel B: per-row scalars ----------------
__global__ void k_scal(const float* __restrict__ a) {
    const int i = blockIdx.x;
    const int tid = threadIdx.x;  // 128
    float v = g_V[(size_t)i * DD + tid];
    float sp = v * a[tid];
    float tp = v * a[DD + tid];
    #pragma unroll
    for (int off = 16; off; off >>= 1) {
        sp += __shfl_down_sync(0xffffffffu, sp, off);
        tp += __shfl_down_sync(0xffffffffu, tp, off);
    }
    __shared__ float rs[4], rt[4];
    int w = tid >> 5;
    if ((tid & 31) == 0) { rs[w] = sp; rt[w] = tp; }
    __syncthreads();
    if (tid == 0) {
        float s = rs[0] + rs[1] + rs[2] + rs[3];
        float t = rt[0] + rt[1] + rt[2] + rt[3];
        g_s[i] = s; g_Es[i] = expf(s); g_Fs[i] = expf(0.01f * s);
        g_t[i] = t; g_Et[i] = expf(t); g_Ft[i] = expf(0.01f * t);
    }
}

// ---------------- Kernel C: pipelined fp16 mma.sync  P @ V ----------------
__global__ __launch_bounds__(256, 2) void k_mma(const int* __restrict__ adj) {
    extern __shared__ char smemc[];
    __half (*sPh)[128][40] = (__half (*)[128][40])(smemc + SPH_OFF);
    __half (*sVh)[128][40] = (__half (*)[128][40])(smemc + SVH_OFF);
    float* sDen            = (float*)(smemc + DEN_OFF);
    const uint32_t svh_base = (uint32_t)__cvta_generic_to_shared(smemc + SVH_OFF);

    const int tid = threadIdx.x;
    const int w   = tid >> 5;
    const int l   = tid & 31;
    const int g   = l >> 2;
    const int t4  = l & 3;
    const int rb  = blockIdx.x * MB;
    const int jsp = blockIdx.y;

    const int mrow = (w & 3) * 32;
    const int ncol = (w >> 2) * 64;

    const int r = tid >> 1;
    const int h = tid & 1;
    const float rowS  = g_s [rb + r];
    const float rowEs = g_Es[rb + r];
    const float rowFs = g_Fs[rb + r];
    const size_t adjrow = (size_t)(rb + r) * NN;

    float denreg = 0.f;

    float acc[2][8][4];
    #pragma unroll
    for (int m = 0; m < 2; m++)
        #pragma unroll
        for (int n = 0; n < 8; n++)
            #pragma unroll
            for (int i = 0; i < 4; i++) acc[m][n][i] = 0.f;

    const int jbase = jsp * JLEN;

    // stage V chunk: each dim row d gets 32 nodes = 64B = 4 cp.async16 at
    // half-offsets 0, 8, 16, 24  (FIX: was 16*q, skipping/overflowing)
    #define STAGE_V(jb_, buf_)                                                    \
        {                                                                         \
            _Pragma("unroll")                                                     \
            for (int it = 0; it < 2; ++it) {                                      \
                int f_ = tid + it * 256;            /* 0..511 */                  \
                int d_ = f_ >> 2, q_ = f_ & 3;                                    \
                uint32_t dst_ = svh_base +                                        \
                    (uint32_t)((((buf_) * 128 + d_) * 40 + 8 * q_) * 2);          \
                cp_async16(dst_, g_VhT + (size_t)d_ * NN + (jb_) + 8 * q_);       \
            }                                                                     \
            cp_commit();                                                          \
        }

    // build 16 cols [16h,16h+16) of row r as fp16 pairs
    #define BUILD_P(jb_, A4_, pb_)                                                \
        {                                                                         \
            float p_[16];                                                         \
            float psum_ = 0.f;                                                    \
            _Pragma("unroll")                                                     \
            for (int q_ = 0; q_ < 4; ++q_) {                                      \
                const int j_ = (jb_) + 16 * h + 4 * q_;                           \
                int4   av  = A4_[q_];                                             \
                float4 tv  = *(const float4*)(g_t  + j_);                         \
                float4 etv = *(const float4*)(g_Et + j_);                         \
                float4 ftv = *(const float4*)(g_Ft + j_);                         \
                p_[4*q_+0] = (av.x > 0) ? ((rowS + tv.x >= 0.f) ? rowEs * etv.x : rowFs * ftv.x) : 0.f; \
                p_[4*q_+1] = (av.y > 0) ? ((rowS + tv.y >= 0.f) ? rowEs * etv.y : rowFs * ftv.y) : 0.f; \
                p_[4*q_+2] = (av.z > 0) ? ((rowS + tv.z >= 0.f) ? rowEs * etv.z : rowFs * ftv.z) : 0.f; \
                p_[4*q_+3] = (av.w > 0) ? ((rowS + tv.w >= 0.f) ? rowEs * etv.w : rowFs * ftv.w) : 0.f; \
                psum_ += (p_[4*q_+0] + p_[4*q_+1]) + (p_[4*q_+2] + p_[4*q_+3]);   \
            }                                                                     \
            uint4 u0_, u1_;                                                       \
            u0_.x = h2u(p_[0],  p_[1]);  u0_.y = h2u(p_[2],  p_[3]);              \
            u0_.z = h2u(p_[4],  p_[5]);  u0_.w = h2u(p_[6],  p_[7]);              \
            u1_.x = h2u(p_[8],  p_[9]);  u1_.y = h2u(p_[10], p_[11]);             \
            u1_.z = h2u(p_[12], p_[13]); u1_.w = h2u(p_[14], p_[15]);             \
            *(uint4*)&sPh[pb_][r][16 * h]     = u0_;                              \
            *(uint4*)&sPh[pb_][r][16 * h + 8] = u1_;                              \
            psum_ += __shfl_down_sync(0xffffffffu, psum_, 1);                     \
            if (h == 0) denreg += psum_;                                          \
        }

    // ---- prologue: chunks 0 and 1 ----
    int4 a4[4];
    {
        STAGE_V(jbase, 0);
        #pragma unroll
        for (int q = 0; q < 4; ++q)
            a4[q] = *(const int4*)(adj + adjrow + jbase + 16 * h + 4 * q);
        BUILD_P(jbase, a4, 0);
        STAGE_V(jbase + KC, 1);
        #pragma unroll
        for (int q = 0; q < 4; ++q)
            a4[q] = *(const int4*)(adj + adjrow + jbase + KC + 16 * h + 4 * q);
        cp_wait0();
        __syncthreads();
    }

    for (int c = 0; c < NC; ++c) {
        const int buf = c & 1;

        // ---- overlapped build of P(c+1) ----
        if (c + 1 < NC) {
            BUILD_P(jbase + (c + 1) * KC, a4, buf ^ 1);
            if (c + 2 < NC) {
                if (w == 0) {
                    const int jn = jbase + (c + 2) * KC + 16 * h;
                    pf_l1(g_t + jn); pf_l1(g_Et + jn); pf_l1(g_Ft + jn);
                }
                #pragma unroll
                for (int q = 0; q < 4; ++q)
                    a4[q] = *(const int4*)(adj + adjrow + jbase + (c + 2) * KC + 16 * h + 4 * q);
            }
        }

        // ---- MMA phase on chunk c: 2 ksteps of k=16 ----
        #pragma unroll
        for (int ks = 0; ks < 2; ++ks) {
            const int k0 = 16 * ks;
            uint32_t afrag[2][4];
            #pragma unroll
            for (int m = 0; m < 2; ++m) {
                const int r0 = mrow + 16 * m;
                afrag[m][0] = *(const uint32_t*)&sPh[buf][r0 + g    ][k0 + 2 * t4    ];
                afrag[m][1] = *(const uint32_t*)&sPh[buf][r0 + g + 8][k0 + 2 * t4    ];
                afrag[m][2] = *(const uint32_t*)&sPh[buf][r0 + g    ][k0 + 2 * t4 + 8];
                afrag[m][3] = *(const uint32_t*)&sPh[buf][r0 + g + 8][k0 + 2 * t4 + 8];
            }
            #pragma unroll
            for (int n = 0; n < 8; ++n) {
                const int n0 = ncol + 8 * n;
                uint32_t b0 = *(const uint32_t*)&sVh[buf][n0 + g][k0 + 2 * t4    ];
                uint32_t b1 = *(const uint32_t*)&sVh[buf][n0 + g][k0 + 2 * t4 + 8];
                mma_f16_16x8x16(acc[0][n], afrag[0], b0, b1);
                mma_f16_16x8x16(acc[1][n], afrag[1], b0, b1);
            }
        }

        if (c + 1 < NC) {
            cp_wait0();
            __syncthreads();
            if (c + 2 < NC)
                STAGE_V(jbase + (c + 2) * KC, buf);
        }
    }

    // ---- epilogue ----
    float* outp = g_parts[jsp];
    #pragma unroll
    for (int m = 0; m < 2; ++m) {
        #pragma unroll
        for (int n = 0; n < 8; ++n) {
            const int row0 = rb + mrow + 16 * m + g;
            const int col  = ncol + 8 * n + 2 * t4;
            *(float2*)(outp + (size_t)row0 * DD + col) =
                make_float2(acc[m][n][0], acc[m][n][1]);
            *(float2*)(outp + (size_t)(row0 + 8) * DD + col) =
                make_float2(acc[m][n][2], acc[m][n][3]);
        }
    }
    __syncthreads();
    if (h == 0) sDen[r] = denreg;
    __syncthreads();
    if (tid < 128) g_dparts[jsp][rb + tid] = sDen[tid];
}

// ---------------- Kernel D: combine partials, normalize, relu ----------------
__global__ void k_final(float* __restrict__ out) {
    int idx = blockIdx.x * 256 + threadIdx.x;
    int r = idx >> 7;
    float dsum = g_dparts[0][r] + g_dparts[1][r] + g_dparts[2][r];
    float v = g_parts[0][idx] + g_parts[1][idx] + g_parts[2][idx];
    out[idx] = fmaxf(v / dsum, 0.f);
}

// ---------------- launch ----------------
extern "C" void kernel_launch(void* const* d_in, const int* in_sizes, int n_in,
                              void* d_out, int out_size) {
    const float* emb = (const float*)d_in[0];
    const int*   adj = (const int*)d_in[1];
    const float* W   = (const float*)d_in[2];
    const float* a   = (const float*)d_in[3];
    float* out = (float*)d_out;

    cudaFuncSetAttribute(k_mma, cudaFuncAttributeMaxDynamicSharedMemorySize, SMEM_BYTES);

    k_transW<<<(DD * DD + 255) / 256, 256>>>(W);
    k_enew<<<NN / 16, 256>>>(emb);
    k_scal<<<NN, 128>>>(a);
    k_vhT<<<dim3(NN / 32, DD / 32), dim3(32, 8)>>>();
    k_mma<<<dim3(MBLK, JSPLIT), 256, SMEM_BYTES>>>(adj);
    k_final<<<(NN * DD) / 256, 256>>>(out);
}